// round 10
// baseline (speedup 1.0000x reference)
#include <cuda_runtime.h>
#include <math.h>

#define VV 10000
#define EE 512
#define HH 1024
#define SS 64
#define BB 64

#define SBH (SS*BB*HH)
#define BH  (BB*HH)

typedef unsigned long long ull;

// ---------------- device scratch ----------------
__device__ float g_X0[3u * SBH];
__device__ float g_H1all[SBH];
__device__ float g_h0[2][BH];   // layer0 hidden, parity: H(t) in g_h0[t&1]
__device__ float g_x1[2][BH];   // fc output, parity t&1
__device__ float g_h1[BH];
__device__ float g_rh0[BH];
__device__ float g_z0[BH];
__device__ float g_rh1[BH];
__device__ float g_z1[BH];

__device__ __forceinline__ float sigm(float x) { return 1.0f / (1.0f + __expf(-x)); }

// ---------------- packed f32x2 helpers (sm_103a FFMA2) ----------------
__device__ __forceinline__ void fma2(ull &c, ull a, ull b) {
    asm("fma.rn.f32x2 %0, %1, %2, %0;" : "+l"(c) : "l"(a), "l"(b));
}
__device__ __forceinline__ void add2(ull &c, ull a) {
    asm("add.rn.f32x2 %0, %0, %1;" : "+l"(c) : "l"(a));
}
__device__ __forceinline__ ull pk2(float lo, float hi) {
    ull r; asm("mov.b64 %0, {%1, %2};" : "=l"(r) : "f"(lo), "f"(hi)); return r;
}
__device__ __forceinline__ void unpk(ull v, float &lo, float &hi) {
    asm("mov.b64 {%0, %1}, %2;" : "=f"(lo), "=f"(hi) : "l"(v));
}

// ---------------- init ----------------
__global__ void k_init(const float* __restrict__ h_init) {
    int i = blockIdx.x * blockDim.x + threadIdx.x;
    if (i < BH) {
        g_h0[0][i] = h_init[i];
        g_h1[i]    = h_init[BH + i];
    }
}

// ---------------- embedding precompute GEMM (64x64x16, packed fma2) ----------------
__global__ __launch_bounds__(256) void k_embed(
    const int* __restrict__ ids, const float* __restrict__ emb,
    const float* __restrict__ Wr, const float* __restrict__ Wz, const float* __restrict__ Wh,
    const float* __restrict__ br, const float* __restrict__ bz, const float* __restrict__ bh)
{
    const int g = blockIdx.z;
    const float* __restrict__ W    = (g == 0) ? Wr : ((g == 1) ? Wz : Wh);
    const float* __restrict__ bias = (g == 0) ? br : ((g == 1) ? bz : bh);
    float* __restrict__ out = g_X0 + (size_t)g * SBH;

    __shared__ __align__(16) float As[16][68];
    __shared__ __align__(16) float Ws[16][64];
    const int tid = threadIdx.x;
    const int bm = blockIdx.y * 64, bn = blockIdx.x * 64;
    const int lr = tid >> 2, lk = (tid & 3) * 4;
    const int wk = tid >> 4, wn = (tid & 15) * 4;
    const int tx = tid & 15, ty = tid >> 4;
    const float* __restrict__ arow = emb + (size_t)ids[bm + lr] * EE + lk;

    ull accp[4][2];
#pragma unroll
    for (int i = 0; i < 4; i++) { accp[i][0] = 0ull; accp[i][1] = 0ull; }

    for (int k0 = 0; k0 < EE; k0 += 16) {
        float4 av = *(const float4*)(arow + k0);
        As[lk + 0][lr] = av.x; As[lk + 1][lr] = av.y;
        As[lk + 2][lr] = av.z; As[lk + 3][lr] = av.w;
        *(float4*)&Ws[wk][wn] = *(const float4*)(W + (size_t)(k0 + wk) * HH + bn + wn);
        __syncthreads();
#pragma unroll
        for (int kk = 0; kk < 16; kk++) {
            float4 a = *(const float4*)&As[kk][ty * 4];
            float4 w = *(const float4*)&Ws[kk][tx * 4];
            ulonglong2 wp = *reinterpret_cast<ulonglong2*>(&w);
            ull a0 = pk2(a.x, a.x), a1 = pk2(a.y, a.y);
            ull a2 = pk2(a.z, a.z), a3 = pk2(a.w, a.w);
            fma2(accp[0][0], a0, wp.x); fma2(accp[0][1], a0, wp.y);
            fma2(accp[1][0], a1, wp.x); fma2(accp[1][1], a1, wp.y);
            fma2(accp[2][0], a2, wp.x); fma2(accp[2][1], a2, wp.y);
            fma2(accp[3][0], a3, wp.x); fma2(accp[3][1], a3, wp.y);
        }
        __syncthreads();
    }
    float4 bv = *(const float4*)(bias + bn + tx * 4);
#pragma unroll
    for (int i = 0; i < 4; i++) {
        float c0, c1, c2, c3;
        unpk(accp[i][0], c0, c1); unpk(accp[i][1], c2, c3);
        int row = bm + ty * 4 + i;
        float* o = out + (size_t)row * HH + bn + tx * 4;
        o[0] = c0 + bv.x; o[1] = c1 + bv.y; o[2] = c2 + bv.z; o[3] = c3 + bv.w;
    }
}

// ---------------- k_out: logits = H1all @ Wout + bout (packed fma2) ----------------
__global__ __launch_bounds__(256) void k_out(
    const float* __restrict__ Wout, const float* __restrict__ bout,
    float* __restrict__ logits)
{
    __shared__ __align__(16) float As[16][68];
    __shared__ __align__(16) float Ws[16][64];
    const int tid = threadIdx.x;
    const int bm = blockIdx.y * 64, bn = blockIdx.x * 64;
    const int lr = tid >> 2, lk = (tid & 3) * 4;
    const int wk = tid >> 4, wn = (tid & 15) * 4;
    const int tx = tid & 15, ty = tid >> 4;
    const float* __restrict__ arow = g_H1all + (size_t)(bm + lr) * HH + lk;
    const bool wok = (bn + wn + 3) < VV;

    ull accp[4][2];
#pragma unroll
    for (int i = 0; i < 4; i++) { accp[i][0] = 0ull; accp[i][1] = 0ull; }

    for (int k0 = 0; k0 < HH; k0 += 16) {
        float4 av = *(const float4*)(arow + k0);
        As[lk + 0][lr] = av.x; As[lk + 1][lr] = av.y;
        As[lk + 2][lr] = av.z; As[lk + 3][lr] = av.w;
        float4 wv;
        const float* wp = Wout + (size_t)(k0 + wk) * VV;
        if (wok) {
            wv = *(const float4*)(wp + bn + wn);
        } else {
            wv.x = (bn + wn + 0 < VV) ? wp[bn + wn + 0] : 0.f;
            wv.y = (bn + wn + 1 < VV) ? wp[bn + wn + 1] : 0.f;
            wv.z = (bn + wn + 2 < VV) ? wp[bn + wn + 2] : 0.f;
            wv.w = (bn + wn + 3 < VV) ? wp[bn + wn + 3] : 0.f;
        }
        *(float4*)&Ws[wk][wn] = wv;
        __syncthreads();
#pragma unroll
        for (int kk = 0; kk < 16; kk++) {
            float4 a = *(const float4*)&As[kk][ty * 4];
            float4 w = *(const float4*)&Ws[kk][tx * 4];
            ulonglong2 wpk = *reinterpret_cast<ulonglong2*>(&w);
            ull a0 = pk2(a.x, a.x), a1 = pk2(a.y, a.y);
            ull a2 = pk2(a.z, a.z), a3 = pk2(a.w, a.w);
            fma2(accp[0][0], a0, wpk.x); fma2(accp[0][1], a0, wpk.y);
            fma2(accp[1][0], a1, wpk.x); fma2(accp[1][1], a1, wpk.y);
            fma2(accp[2][0], a2, wpk.x); fma2(accp[2][1], a2, wpk.y);
            fma2(accp[3][0], a3, wpk.x); fma2(accp[3][1], a3, wpk.y);
        }
        __syncthreads();
    }
#pragma unroll
    for (int i = 0; i < 4; i++) {
        float c[4];
        unpk(accp[i][0], c[0], c[1]); unpk(accp[i][1], c[2], c[3]);
        int row = bm + ty * 4 + i;
#pragma unroll
        for (int j = 0; j < 4; j++) {
            int col = bn + tx * 4 + j;
            if (col < VV) logits[(size_t)row * VV + col] = c[j] + bout[col];
        }
    }
}

// ================= stage GEMM core: 512 threads, 64-CTA grids =================
// C tile [64 rows x NC cols]. NC=16: 8 K-teams x 64 thr; NC=32: 4 K-teams x 128 thr.
// Thread tile 8 rows x 2 cols (8 packed accumulators), BK=8 per chunk, double-buffered.
// A split across K: first KT1 from A1, rest from A2 (both lda = HH).
#define SM16 ((8*2*8*68 + 8*2*8*32) * 4 + 7*64*8*8)    // 79872 B
#define SM32 ((4*2*8*68 + 4*2*8*64) * 4 + 3*128*8*8)   // 58368 B

template<int NC, int KT, int KT1>
__device__ __forceinline__ void stage_core(
    const float* __restrict__ A1, const float* __restrict__ A2,
    const float* __restrict__ W, int bn, ull* __restrict__ acc)
{
    constexpr int NCP = NC / 2;
    constexpr int TPT = 8 * NCP;              // 64 or 128 threads per team
    constexpr int NTEAM = 512 / TPT;          // 8 or 4
    constexpr int KTEAM = KT / NTEAM;
    constexpr int CH = KTEAM / 8;
    constexpr int ASF = NTEAM * 2 * 8 * 68;
    constexpr int WSF = NTEAM * 2 * 8 * 2 * NC;

    extern __shared__ float dyn[];
    float* As = dyn;
    float* Ws = dyn + ASF;
    ull*   Pq = (ull*)(dyn + ASF + WSF);

    const int tid = threadIdx.x;
    const int team = tid / TPT, u = tid % TPT;
    const int koff = team * KTEAM;
    const float* __restrict__ Ab = (koff < KT1) ? (A1 + koff) : (A2 + (koff - KT1));

    const int arow = (NC == 16) ? u : (u >> 1);
    const int akh  = (NC == 16) ? 0 : ((u & 1) * 4);
    const int wr   = (NC == 16) ? (u >> 3) : (u >> 4);
    const int wq   = (NC == 16) ? (u & 7)  : (u & 15);
    const int rg = u / NCP, cp = u % NCP;

    const float* __restrict__ Ap = Ab + (size_t)arow * HH + akh;
    const float* __restrict__ Wp = W + (size_t)(koff + wr) * HH + bn + wq * 2;

#pragma unroll
    for (int i = 0; i < 8; i++) acc[i] = 0ull;

    float a_st[(NC == 16) ? 8 : 4];
    float w0s, w1s;

    // prologue: chunk 0 -> regs -> smem buf0
    {
        float4 v0 = *(const float4*)(Ap);
        a_st[0]=v0.x; a_st[1]=v0.y; a_st[2]=v0.z; a_st[3]=v0.w;
        if (NC == 16) {
            float4 v1 = *(const float4*)(Ap + 4);
            a_st[4]=v1.x; a_st[5]=v1.y; a_st[6]=v1.z; a_st[7]=v1.w;
        }
        float2 wv = *(const float2*)(Wp);
        w0s = wv.x; w1s = wv.y;
    }
    {
        float* Abs = As + (team * 2) * 544;
        if (NC == 16) {
#pragma unroll
            for (int j = 0; j < 8; j++) Abs[j * 68 + u] = a_st[j];
        } else {
#pragma unroll
            for (int j = 0; j < 4; j++) Abs[(akh + j) * 68 + arow] = a_st[j];
        }
        float* Wd = Ws + (team * 2) * (16 * NC) + wr * (2 * NC) + wq * 4;
        Wd[0] = w0s; Wd[1] = w0s; Wd[2] = w1s; Wd[3] = w1s;
    }
    __syncthreads();

    int buf = 0;
    for (int c = 0; c < CH; ++c) {
        const bool more = (c + 1 < CH);
        if (more) {
            const int k0 = (c + 1) * 8;
            float4 v0 = *(const float4*)(Ap + k0);
            a_st[0]=v0.x; a_st[1]=v0.y; a_st[2]=v0.z; a_st[3]=v0.w;
            if (NC == 16) {
                float4 v1 = *(const float4*)(Ap + k0 + 4);
                a_st[4]=v1.x; a_st[5]=v1.y; a_st[6]=v1.z; a_st[7]=v1.w;
            }
            float2 wv = *(const float2*)(Wp + (size_t)k0 * HH);
            w0s = wv.x; w1s = wv.y;
        }
        {
            const float* Ac = As + (team * 2 + buf) * 544 + rg * 8;
            const float* Wc = Ws + (team * 2 + buf) * (16 * NC) + cp * 4;
#pragma unroll
            for (int kk = 0; kk < 8; ++kk) {
                float4 lo = *(const float4*)(Ac + kk * 68);
                float4 hi = *(const float4*)(Ac + kk * 68 + 4);
                float4 wd = *(const float4*)(Wc + kk * 2 * NC);
                ulonglong2 pl = *reinterpret_cast<ulonglong2*>(&lo);
                ulonglong2 ph = *reinterpret_cast<ulonglong2*>(&hi);
                ulonglong2 wp = *reinterpret_cast<ulonglong2*>(&wd);
                fma2(acc[0], pl.x, wp.x); fma2(acc[1], pl.x, wp.y);
                fma2(acc[2], pl.y, wp.x); fma2(acc[3], pl.y, wp.y);
                fma2(acc[4], ph.x, wp.x); fma2(acc[5], ph.x, wp.y);
                fma2(acc[6], ph.y, wp.x); fma2(acc[7], ph.y, wp.y);
            }
        }
        if (more) {
            float* Abs = As + (team * 2 + (buf ^ 1)) * 544;
            if (NC == 16) {
#pragma unroll
                for (int j = 0; j < 8; j++) Abs[j * 68 + u] = a_st[j];
            } else {
#pragma unroll
                for (int j = 0; j < 4; j++) Abs[(akh + j) * 68 + arow] = a_st[j];
            }
            float* Wd = Ws + (team * 2 + (buf ^ 1)) * (16 * NC) + wr * (2 * NC) + wq * 4;
            Wd[0] = w0s; Wd[1] = w0s; Wd[2] = w1s; Wd[3] = w1s;
            __syncthreads();
            buf ^= 1;
        }
    }

    // reduction: teams 1..NTEAM-1 -> Pq; team 0 accumulates
    if (team != 0) {
        ull* p = Pq + (size_t)(team - 1) * TPT * 8 + u * 8;
#pragma unroll
        for (int i = 0; i < 8; i++) p[i] = acc[i];
    }
    __syncthreads();
    if (team == 0) {
#pragma unroll 1
        for (int r = 0; r < NTEAM - 1; r++) {
            ull* p = Pq + (size_t)r * TPT * 8 + u * 8;
#pragma unroll
            for (int i = 0; i < 8; i++) add2(acc[i], p[i]);
        }
    }
}

// ---------------- stage kernels (all grid=64, block=512) ----------------

// r0 & z0 folded into N=2048: gate = col>>10. Writes rh0 / z0.
__global__ __launch_bounds__(512, 1) void k_g0(int p, int ts,
    const float* __restrict__ Wr0, const float* __restrict__ Wz0)
{
    const int g = blockIdx.x * 32;
    const int gate = g >> 10, bn = g & (HH - 1);
    const float* W = (gate ? Wz0 : Wr0) + (size_t)EE * HH;
    ull acc[8];
    stage_core<32, HH, HH>(g_h0[p], g_h0[p], W, bn, acc);
    if (threadIdx.x < 128) {
        const int u = threadIdx.x, rg = u >> 4, cp = u & 15;
        const float* X = g_X0 + (size_t)gate * SBH + (size_t)ts * BH;
        const float* h0 = g_h0[p];
#pragma unroll
        for (int q = 0; q < 4; q++)
#pragma unroll
            for (int c = 0; c < 2; c++) {
                float va, vb; unpk(acc[2 * q + c], va, vb);
                int r = rg * 8 + 2 * q, n = bn + cp * 2 + c;
                int i0 = r * HH + n, i1 = i0 + HH;
                float s0 = sigm(va + X[i0]);
                float s1 = sigm(vb + X[i1]);
                if (gate == 0) { g_rh0[i0] = s0 * h0[i0]; g_rh0[i1] = s1 * h0[i1]; }
                else           { g_z0[i0] = s0;           g_z0[i1] = s1; }
            }
    }
}

// hh0; h0[p^1] = (1-z0)*h0[p] + z0*hh0
__global__ __launch_bounds__(512, 1) void k_c0(int p, int ts, const float* __restrict__ Wh0)
{
    const int bn = blockIdx.x * 16;
    ull acc[8];
    stage_core<16, HH, HH>(g_rh0, g_rh0, Wh0 + (size_t)EE * HH, bn, acc);
    if (threadIdx.x < 64) {
        const int u = threadIdx.x, rg = u >> 3, cp = u & 7;
        const float* X = g_X0 + 2ull * SBH + (size_t)ts * BH;
        const float* h0 = g_h0[p];
        float* h0n = g_h0[p ^ 1];
#pragma unroll
        for (int q = 0; q < 4; q++)
#pragma unroll
            for (int c = 0; c < 2; c++) {
                float va, vb; unpk(acc[2 * q + c], va, vb);
                int r = rg * 8 + 2 * q, n = bn + cp * 2 + c;
                int i0 = r * HH + n, i1 = i0 + HH;
                float za = g_z0[i0], zb = g_z0[i1];
                h0n[i0] = (1.f - za) * h0[i0] + za * sigm(va + X[i0]);
                h0n[i1] = (1.f - zb) * h0[i1] + zb * sigm(vb + X[i1]);
            }
    }
}

// x1[px] = sigm(h0[ph] @ Wfc + bfc)
__global__ __launch_bounds__(512, 1) void k_fc(int ph, int px,
    const float* __restrict__ Wfc, const float* __restrict__ bfc)
{
    const int bn = blockIdx.x * 16;
    ull acc[8];
    stage_core<16, HH, HH>(g_h0[ph], g_h0[ph], Wfc, bn, acc);
    if (threadIdx.x < 64) {
        const int u = threadIdx.x, rg = u >> 3, cp = u & 7;
        float* x1 = g_x1[px];
#pragma unroll
        for (int q = 0; q < 4; q++)
#pragma unroll
            for (int c = 0; c < 2; c++) {
                float va, vb; unpk(acc[2 * q + c], va, vb);
                int r = rg * 8 + 2 * q, n = bn + cp * 2 + c;
                x1[r * HH + n]       = sigm(va + bfc[n]);
                x1[(r + 1) * HH + n] = sigm(vb + bfc[n]);
            }
    }
}

// r1 & z1 over [x1[p] | h1], K=2048, gates folded into N=2048. Writes rh1 / z1.
__global__ __launch_bounds__(512, 1) void k_g1(int p,
    const float* __restrict__ Wr1, const float* __restrict__ Wz1,
    const float* __restrict__ br1, const float* __restrict__ bz1)
{
    const int g = blockIdx.x * 32;
    const int gate = g >> 10, bn = g & (HH - 1);
    const float* W = gate ? Wz1 : Wr1;
    ull acc[8];
    stage_core<32, 2 * HH, HH>(g_x1[p], g_h1, W, bn, acc);
    if (threadIdx.x < 128) {
        const int u = threadIdx.x, rg = u >> 4, cp = u & 15;
        const float* bias = gate ? bz1 : br1;
#pragma unroll
        for (int q = 0; q < 4; q++)
#pragma unroll
            for (int c = 0; c < 2; c++) {
                float va, vb; unpk(acc[2 * q + c], va, vb);
                int r = rg * 8 + 2 * q, n = bn + cp * 2 + c;
                int i0 = r * HH + n, i1 = i0 + HH;
                float s0 = sigm(va + bias[n]);
                float s1 = sigm(vb + bias[n]);
                if (gate == 0) { g_rh1[i0] = s0 * g_h1[i0]; g_rh1[i1] = s1 * g_h1[i1]; }
                else           { g_z1[i0] = s0;             g_z1[i1] = s1; }
            }
    }
}

// hh1 over [x1[p] | rh1]; h1 = (1-z1)h1 + z1*hh1; store H1all[ts]
__global__ __launch_bounds__(512, 1) void k_c1(int p, int ts,
    const float* __restrict__ Wh1, const float* __restrict__ bh1)
{
    const int bn = blockIdx.x * 16;
    ull acc[8];
    stage_core<16, 2 * HH, HH>(g_x1[p], g_rh1, Wh1, bn, acc);
    if (threadIdx.x < 64) {
        const int u = threadIdx.x, rg = u >> 3, cp = u & 7;
#pragma unroll
        for (int q = 0; q < 4; q++)
#pragma unroll
            for (int c = 0; c < 2; c++) {
                float va, vb; unpk(acc[2 * q + c], va, vb);
                int r = rg * 8 + 2 * q, n = bn + cp * 2 + c;
#pragma unroll
                for (int s = 0; s < 2; s++) {
                    int idx = (r + s) * HH + n;
                    float hv = (s == 0) ? va : vb;
                    float hh = sigm(hv + bh1[n]);
                    float h1 = g_h1[idx], z = g_z1[idx];
                    float hn = (1.f - z) * h1 + z * hh;
                    g_h1[idx] = hn;
                    g_H1all[(size_t)ts * BH + idx] = hn;
                }
            }
    }
}

// h_final = [h0, h1]  (SS even -> final h0 parity 0)
__global__ void k_hfinal(float* __restrict__ out) {
    int i = blockIdx.x * blockDim.x + threadIdx.x;
    if (i < BH) {
        out[i]      = g_h0[0][i];
        out[BH + i] = g_h1[i];
    }
}

extern "C" void kernel_launch(void* const* d_in, const int* in_sizes, int n_in,
                              void* d_out, int out_size)
{
    const int*   ids    = (const int*)d_in[0];
    const float* h_init = (const float*)d_in[1];
    const float* emb    = (const float*)d_in[2];
    const float* Wr0 = (const float*)d_in[3],  *Wz0 = (const float*)d_in[4],  *Wh0 = (const float*)d_in[5];
    const float* br0 = (const float*)d_in[6],  *bz0 = (const float*)d_in[7],  *bh0 = (const float*)d_in[8];
    const float* Wr1 = (const float*)d_in[9],  *Wz1 = (const float*)d_in[10], *Wh1 = (const float*)d_in[11];
    const float* br1 = (const float*)d_in[12], *bz1 = (const float*)d_in[13], *bh1 = (const float*)d_in[14];
    const float* Wfc = (const float*)d_in[15], *bfc = (const float*)d_in[16];
    const float* Wout = (const float*)d_in[17], *bout = (const float*)d_in[18];
    float* out = (float*)d_out;

    // one-time host objects (created on the first, non-captured, correctness call)
    static bool s_init = false;
    static cudaStream_t sB, sC;
    static cudaEvent_t evStart, evC0, evFcP[2], evC1P[2], evB, evC;
    if (!s_init) {
        cudaStreamCreateWithFlags(&sB, cudaStreamNonBlocking);
        cudaStreamCreateWithFlags(&sC, cudaStreamNonBlocking);
        cudaEventCreateWithFlags(&evStart,  cudaEventDisableTiming);
        cudaEventCreateWithFlags(&evC0,     cudaEventDisableTiming);
        cudaEventCreateWithFlags(&evFcP[0], cudaEventDisableTiming);
        cudaEventCreateWithFlags(&evFcP[1], cudaEventDisableTiming);
        cudaEventCreateWithFlags(&evC1P[0], cudaEventDisableTiming);
        cudaEventCreateWithFlags(&evC1P[1], cudaEventDisableTiming);
        cudaEventCreateWithFlags(&evB,      cudaEventDisableTiming);
        cudaEventCreateWithFlags(&evC,      cudaEventDisableTiming);
        s_init = true;
    }

    cudaFuncSetAttribute(k_g0, cudaFuncAttributeMaxDynamicSharedMemorySize, SM32);
    cudaFuncSetAttribute(k_g1, cudaFuncAttributeMaxDynamicSharedMemorySize, SM32);
    cudaFuncSetAttribute(k_c0, cudaFuncAttributeMaxDynamicSharedMemorySize, SM16);
    cudaFuncSetAttribute(k_fc, cudaFuncAttributeMaxDynamicSharedMemorySize, SM16);
    cudaFuncSetAttribute(k_c1, cudaFuncAttributeMaxDynamicSharedMemorySize, SM16);

    k_init<<<(BH + 255) / 256, 256>>>(h_init);
    k_embed<<<dim3(HH / 64, (SS * BB) / 64, 3), 256>>>(ids, emb, Wr0, Wz0, Wh0, br0, bz0, bh0);

    // fork sB / sC off the main (legacy) stream
    cudaEventRecord(evStart, 0);
    cudaStreamWaitEvent(sB, evStart, 0);
    cudaStreamWaitEvent(sC, evStart, 0);
    // pre-record parity handles so the first waits are valid in capture
    cudaEventRecord(evFcP[0], sB); cudaEventRecord(evFcP[1], sB);
    cudaEventRecord(evC1P[0], sC); cudaEventRecord(evC1P[1], sC);

    for (int t = 0; t < SS; ++t) {
        const int p = t & 1;
        // ---- layer-0 chain on the main stream ----
        if (t >= 2) cudaStreamWaitEvent(0, evFcP[p], 0);   // WAR: c0(t) overwrites h0 read by fc(t-2)
        k_g0<<<64, 512, SM32, 0>>>(p, t, Wr0, Wz0);
        k_c0<<<64, 512, SM16, 0>>>(p, t, Wh0);
        cudaEventRecord(evC0, 0);
        // ---- fc on stream B ----
        cudaStreamWaitEvent(sB, evC0, 0);
        if (t >= 2) cudaStreamWaitEvent(sB, evC1P[p], 0);  // WAR: fc(t) overwrites x1 read by g1/c1(t-2)
        k_fc<<<64, 512, SM16, sB>>>(p ^ 1, p, Wfc, bfc);
        cudaEventRecord(evFcP[p], sB);
        // ---- layer-1 chain on stream C ----
        cudaStreamWaitEvent(sC, evFcP[p], 0);
        k_g1<<<64, 512, SM32, sC>>>(p, Wr1, Wz1, br1, bz1);
        k_c1<<<64, 512, SM16, sC>>>(p, t, Wh1, bh1);
        cudaEventRecord(evC1P[p], sC);
    }

    // join
    cudaEventRecord(evB, sB);
    cudaEventRecord(evC, sC);
    cudaStreamWaitEvent(0, evB, 0);
    cudaStreamWaitEvent(0, evC, 0);

    k_out<<<dim3((VV + 63) / 64, (SS * BB) / 64), 256>>>(Wout, bout, out);
    k_hfinal<<<(BH + 255) / 256, 256>>>(out + (size_t)SS * BB * VV);
}

// round 11
// speedup vs baseline: 1.6289x; 1.6289x over previous
#include <cuda_runtime.h>
#include <math.h>

#define VV 10000
#define EE 512
#define HH 1024
#define SS 64
#define BB 64

#define SBH (SS*BB*HH)
#define BH  (BB*HH)

typedef unsigned long long ull;

// ---------------- device scratch ----------------
__device__ float g_X0[3u * SBH];
__device__ float g_H1all[SBH];
__device__ float g_h0[2][BH];   // layer0 hidden, parity: H(t) in g_h0[t&1]
__device__ float g_x1[2][BH];   // fc output, parity t&1
__device__ float g_h1[BH];
__device__ float g_rh0[BH];
__device__ float g_z0[BH];
__device__ float g_rh1[BH];
__device__ float g_z1[BH];

__device__ __forceinline__ float sigm(float x) { return 1.0f / (1.0f + __expf(-x)); }

// ---------------- packed f32x2 helpers (sm_103a FFMA2) ----------------
__device__ __forceinline__ void fma2(ull &c, ull a, ull b) {
    asm("fma.rn.f32x2 %0, %1, %2, %0;" : "+l"(c) : "l"(a), "l"(b));
}
__device__ __forceinline__ void add2(ull &c, ull a) {
    asm("add.rn.f32x2 %0, %0, %1;" : "+l"(c) : "l"(a));
}
__device__ __forceinline__ ull pk2(float lo, float hi) {
    ull r; asm("mov.b64 %0, {%1, %2};" : "=l"(r) : "f"(lo), "f"(hi)); return r;
}
__device__ __forceinline__ void unpk(ull v, float &lo, float &hi) {
    asm("mov.b64 {%0, %1}, %2;" : "=f"(lo), "=f"(hi) : "l"(v));
}

// ---------------- init ----------------
__global__ void k_init(const float* __restrict__ h_init) {
    int i = blockIdx.x * blockDim.x + threadIdx.x;
    if (i < BH) {
        g_h0[0][i] = h_init[i];
        g_h1[i]    = h_init[BH + i];
    }
}

// ---------------- embedding precompute GEMM (64x64x16, packed fma2) ----------------
__global__ __launch_bounds__(256) void k_embed(
    const int* __restrict__ ids, const float* __restrict__ emb,
    const float* __restrict__ Wr, const float* __restrict__ Wz, const float* __restrict__ Wh,
    const float* __restrict__ br, const float* __restrict__ bz, const float* __restrict__ bh)
{
    const int g = blockIdx.z;
    const float* __restrict__ W    = (g == 0) ? Wr : ((g == 1) ? Wz : Wh);
    const float* __restrict__ bias = (g == 0) ? br : ((g == 1) ? bz : bh);
    float* __restrict__ out = g_X0 + (size_t)g * SBH;

    __shared__ __align__(16) float As[16][68];
    __shared__ __align__(16) float Ws[16][64];
    const int tid = threadIdx.x;
    const int bm = blockIdx.y * 64, bn = blockIdx.x * 64;
    const int lr = tid >> 2, lk = (tid & 3) * 4;
    const int wk = tid >> 4, wn = (tid & 15) * 4;
    const int tx = tid & 15, ty = tid >> 4;
    const float* __restrict__ arow = emb + (size_t)ids[bm + lr] * EE + lk;

    ull accp[4][2];
#pragma unroll
    for (int i = 0; i < 4; i++) { accp[i][0] = 0ull; accp[i][1] = 0ull; }

    for (int k0 = 0; k0 < EE; k0 += 16) {
        float4 av = *(const float4*)(arow + k0);
        As[lk + 0][lr] = av.x; As[lk + 1][lr] = av.y;
        As[lk + 2][lr] = av.z; As[lk + 3][lr] = av.w;
        *(float4*)&Ws[wk][wn] = *(const float4*)(W + (size_t)(k0 + wk) * HH + bn + wn);
        __syncthreads();
#pragma unroll
        for (int kk = 0; kk < 16; kk++) {
            float4 a = *(const float4*)&As[kk][ty * 4];
            float4 w = *(const float4*)&Ws[kk][tx * 4];
            ulonglong2 wp = *reinterpret_cast<ulonglong2*>(&w);
            ull a0 = pk2(a.x, a.x), a1 = pk2(a.y, a.y);
            ull a2 = pk2(a.z, a.z), a3 = pk2(a.w, a.w);
            fma2(accp[0][0], a0, wp.x); fma2(accp[0][1], a0, wp.y);
            fma2(accp[1][0], a1, wp.x); fma2(accp[1][1], a1, wp.y);
            fma2(accp[2][0], a2, wp.x); fma2(accp[2][1], a2, wp.y);
            fma2(accp[3][0], a3, wp.x); fma2(accp[3][1], a3, wp.y);
        }
        __syncthreads();
    }
    float4 bv = *(const float4*)(bias + bn + tx * 4);
#pragma unroll
    for (int i = 0; i < 4; i++) {
        float c0, c1, c2, c3;
        unpk(accp[i][0], c0, c1); unpk(accp[i][1], c2, c3);
        int row = bm + ty * 4 + i;
        float* o = out + (size_t)row * HH + bn + tx * 4;
        o[0] = c0 + bv.x; o[1] = c1 + bv.y; o[2] = c2 + bv.z; o[3] = c3 + bv.w;
    }
}

// ---------------- k_out: logits = H1all @ Wout + bout (packed fma2) ----------------
__global__ __launch_bounds__(256) void k_out(
    const float* __restrict__ Wout, const float* __restrict__ bout,
    float* __restrict__ logits)
{
    __shared__ __align__(16) float As[16][68];
    __shared__ __align__(16) float Ws[16][64];
    const int tid = threadIdx.x;
    const int bm = blockIdx.y * 64, bn = blockIdx.x * 64;
    const int lr = tid >> 2, lk = (tid & 3) * 4;
    const int wk = tid >> 4, wn = (tid & 15) * 4;
    const int tx = tid & 15, ty = tid >> 4;
    const float* __restrict__ arow = g_H1all + (size_t)(bm + lr) * HH + lk;
    const bool wok = (bn + wn + 3) < VV;

    ull accp[4][2];
#pragma unroll
    for (int i = 0; i < 4; i++) { accp[i][0] = 0ull; accp[i][1] = 0ull; }

    for (int k0 = 0; k0 < HH; k0 += 16) {
        float4 av = *(const float4*)(arow + k0);
        As[lk + 0][lr] = av.x; As[lk + 1][lr] = av.y;
        As[lk + 2][lr] = av.z; As[lk + 3][lr] = av.w;
        float4 wv;
        const float* wp = Wout + (size_t)(k0 + wk) * VV;
        if (wok) {
            wv = *(const float4*)(wp + bn + wn);
        } else {
            wv.x = (bn + wn + 0 < VV) ? wp[bn + wn + 0] : 0.f;
            wv.y = (bn + wn + 1 < VV) ? wp[bn + wn + 1] : 0.f;
            wv.z = (bn + wn + 2 < VV) ? wp[bn + wn + 2] : 0.f;
            wv.w = (bn + wn + 3 < VV) ? wp[bn + wn + 3] : 0.f;
        }
        *(float4*)&Ws[wk][wn] = wv;
        __syncthreads();
#pragma unroll
        for (int kk = 0; kk < 16; kk++) {
            float4 a = *(const float4*)&As[kk][ty * 4];
            float4 w = *(const float4*)&Ws[kk][tx * 4];
            ulonglong2 wpk = *reinterpret_cast<ulonglong2*>(&w);
            ull a0 = pk2(a.x, a.x), a1 = pk2(a.y, a.y);
            ull a2 = pk2(a.z, a.z), a3 = pk2(a.w, a.w);
            fma2(accp[0][0], a0, wpk.x); fma2(accp[0][1], a0, wpk.y);
            fma2(accp[1][0], a1, wpk.x); fma2(accp[1][1], a1, wpk.y);
            fma2(accp[2][0], a2, wpk.x); fma2(accp[2][1], a2, wpk.y);
            fma2(accp[3][0], a3, wpk.x); fma2(accp[3][1], a3, wpk.y);
        }
        __syncthreads();
    }
#pragma unroll
    for (int i = 0; i < 4; i++) {
        float c[4];
        unpk(accp[i][0], c[0], c[1]); unpk(accp[i][1], c[2], c[3]);
        int row = bm + ty * 4 + i;
#pragma unroll
        for (int j = 0; j < 4; j++) {
            int col = bn + tx * 4 + j;
            if (col < VV) logits[(size_t)row * VV + col] = c[j] + bout[col];
        }
    }
}

// ================= stage GEMM core: 512 threads, 64-CTA grids =================
// C tile [64 rows x NC cols]. NC=16: 8 K-teams x 64 thr; NC=32: 4 K-teams x 128 thr.
// Thread tile 8 rows x 2 cols (8 packed accumulators), BK=8 per chunk, double-buffered.
// A split across K: first KT1 from A1, rest from A2 (both lda = HH).
#define SM16 ((8*2*8*68 + 8*2*8*32) * 4 + 7*64*8*8)    // 79872 B
#define SM32 ((4*2*8*68 + 4*2*8*64) * 4 + 3*128*8*8)   // 58368 B

template<int NC, int KT, int KT1>
__device__ __forceinline__ void stage_core(
    const float* __restrict__ A1, const float* __restrict__ A2,
    const float* __restrict__ W, int bn, ull* __restrict__ acc)
{
    constexpr int NCP = NC / 2;
    constexpr int TPT = 8 * NCP;              // 64 or 128 threads per team
    constexpr int NTEAM = 512 / TPT;          // 8 or 4
    constexpr int KTEAM = KT / NTEAM;
    constexpr int CH = KTEAM / 8;
    constexpr int ASF = NTEAM * 2 * 8 * 68;
    constexpr int WSF = NTEAM * 2 * 8 * 2 * NC;

    extern __shared__ float dyn[];
    float* As = dyn;
    float* Ws = dyn + ASF;
    ull*   Pq = (ull*)(dyn + ASF + WSF);

    const int tid = threadIdx.x;
    const int team = tid / TPT, u = tid % TPT;
    const int koff = team * KTEAM;
    const float* __restrict__ Ab = (koff < KT1) ? (A1 + koff) : (A2 + (koff - KT1));

    const int arow = (NC == 16) ? u : (u >> 1);
    const int akh  = (NC == 16) ? 0 : ((u & 1) * 4);
    const int wr   = (NC == 16) ? (u >> 3) : (u >> 4);
    const int wq   = (NC == 16) ? (u & 7)  : (u & 15);
    const int rg = u / NCP, cp = u % NCP;

    const float* __restrict__ Ap = Ab + (size_t)arow * HH + akh;
    const float* __restrict__ Wp = W + (size_t)(koff + wr) * HH + bn + wq * 2;

#pragma unroll
    for (int i = 0; i < 8; i++) acc[i] = 0ull;

    float a_st[(NC == 16) ? 8 : 4];
    float w0s, w1s;

    // prologue: chunk 0 -> regs -> smem buf0
    {
        float4 v0 = *(const float4*)(Ap);
        a_st[0]=v0.x; a_st[1]=v0.y; a_st[2]=v0.z; a_st[3]=v0.w;
        if (NC == 16) {
            float4 v1 = *(const float4*)(Ap + 4);
            a_st[4]=v1.x; a_st[5]=v1.y; a_st[6]=v1.z; a_st[7]=v1.w;
        }
        float2 wv = *(const float2*)(Wp);
        w0s = wv.x; w1s = wv.y;
    }
    {
        float* Abs = As + (team * 2) * 544;
        if (NC == 16) {
#pragma unroll
            for (int j = 0; j < 8; j++) Abs[j * 68 + u] = a_st[j];
        } else {
#pragma unroll
            for (int j = 0; j < 4; j++) Abs[(akh + j) * 68 + arow] = a_st[j];
        }
        float* Wd = Ws + (team * 2) * (16 * NC) + wr * (2 * NC) + wq * 4;
        Wd[0] = w0s; Wd[1] = w0s; Wd[2] = w1s; Wd[3] = w1s;
    }
    __syncthreads();

    int buf = 0;
    for (int c = 0; c < CH; ++c) {
        const bool more = (c + 1 < CH);
        if (more) {
            const int k0 = (c + 1) * 8;
            float4 v0 = *(const float4*)(Ap + k0);
            a_st[0]=v0.x; a_st[1]=v0.y; a_st[2]=v0.z; a_st[3]=v0.w;
            if (NC == 16) {
                float4 v1 = *(const float4*)(Ap + k0 + 4);
                a_st[4]=v1.x; a_st[5]=v1.y; a_st[6]=v1.z; a_st[7]=v1.w;
            }
            float2 wv = *(const float2*)(Wp + (size_t)k0 * HH);
            w0s = wv.x; w1s = wv.y;
        }
        {
            const float* Ac = As + (team * 2 + buf) * 544 + rg * 8;
            const float* Wc = Ws + (team * 2 + buf) * (16 * NC) + cp * 4;
#pragma unroll
            for (int kk = 0; kk < 8; ++kk) {
                float4 lo = *(const float4*)(Ac + kk * 68);
                float4 hi = *(const float4*)(Ac + kk * 68 + 4);
                float4 wd = *(const float4*)(Wc + kk * 2 * NC);
                ulonglong2 pl = *reinterpret_cast<ulonglong2*>(&lo);
                ulonglong2 ph = *reinterpret_cast<ulonglong2*>(&hi);
                ulonglong2 wp = *reinterpret_cast<ulonglong2*>(&wd);
                fma2(acc[0], pl.x, wp.x); fma2(acc[1], pl.x, wp.y);
                fma2(acc[2], pl.y, wp.x); fma2(acc[3], pl.y, wp.y);
                fma2(acc[4], ph.x, wp.x); fma2(acc[5], ph.x, wp.y);
                fma2(acc[6], ph.y, wp.x); fma2(acc[7], ph.y, wp.y);
            }
        }
        if (more) {
            float* Abs = As + (team * 2 + (buf ^ 1)) * 544;
            if (NC == 16) {
#pragma unroll
                for (int j = 0; j < 8; j++) Abs[j * 68 + u] = a_st[j];
            } else {
#pragma unroll
                for (int j = 0; j < 4; j++) Abs[(akh + j) * 68 + arow] = a_st[j];
            }
            float* Wd = Ws + (team * 2 + (buf ^ 1)) * (16 * NC) + wr * (2 * NC) + wq * 4;
            Wd[0] = w0s; Wd[1] = w0s; Wd[2] = w1s; Wd[3] = w1s;
            __syncthreads();
            buf ^= 1;
        }
    }

    // reduction: teams 1..NTEAM-1 -> Pq; team 0 accumulates
    if (team != 0) {
        ull* p = Pq + (size_t)(team - 1) * TPT * 8 + u * 8;
#pragma unroll
        for (int i = 0; i < 8; i++) p[i] = acc[i];
    }
    __syncthreads();
    if (team == 0) {
#pragma unroll 1
        for (int r = 0; r < NTEAM - 1; r++) {
            ull* p = Pq + (size_t)r * TPT * 8 + u * 8;
#pragma unroll
            for (int i = 0; i < 8; i++) add2(acc[i], p[i]);
        }
    }
}

// ---------------- stage kernels (all grid=64, block=512) ----------------

// r0 & z0 folded into N=2048: gate = col>>10. Writes rh0 / z0.
__global__ __launch_bounds__(512, 1) void k_g0(int p, int ts,
    const float* __restrict__ Wr0, const float* __restrict__ Wz0)
{
    const int g = blockIdx.x * 32;
    const int gate = g >> 10, bn = g & (HH - 1);
    const float* W = (gate ? Wz0 : Wr0) + (size_t)EE * HH;
    ull acc[8];
    stage_core<32, HH, HH>(g_h0[p], g_h0[p], W, bn, acc);
    if (threadIdx.x < 128) {
        const int u = threadIdx.x, rg = u >> 4, cp = u & 15;
        const float* X = g_X0 + (size_t)gate * SBH + (size_t)ts * BH;
        const float* h0 = g_h0[p];
#pragma unroll
        for (int q = 0; q < 4; q++)
#pragma unroll
            for (int c = 0; c < 2; c++) {
                float va, vb; unpk(acc[2 * q + c], va, vb);
                int r = rg * 8 + 2 * q, n = bn + cp * 2 + c;
                int i0 = r * HH + n, i1 = i0 + HH;
                float s0 = sigm(va + X[i0]);
                float s1 = sigm(vb + X[i1]);
                if (gate == 0) { g_rh0[i0] = s0 * h0[i0]; g_rh0[i1] = s1 * h0[i1]; }
                else           { g_z0[i0] = s0;           g_z0[i1] = s1; }
            }
    }
}

// hh0; h0[p^1] = (1-z0)*h0[p] + z0*hh0
__global__ __launch_bounds__(512, 1) void k_c0(int p, int ts, const float* __restrict__ Wh0)
{
    const int bn = blockIdx.x * 16;
    ull acc[8];
    stage_core<16, HH, HH>(g_rh0, g_rh0, Wh0 + (size_t)EE * HH, bn, acc);
    if (threadIdx.x < 64) {
        const int u = threadIdx.x, rg = u >> 3, cp = u & 7;
        const float* X = g_X0 + 2ull * SBH + (size_t)ts * BH;
        const float* h0 = g_h0[p];
        float* h0n = g_h0[p ^ 1];
#pragma unroll
        for (int q = 0; q < 4; q++)
#pragma unroll
            for (int c = 0; c < 2; c++) {
                float va, vb; unpk(acc[2 * q + c], va, vb);
                int r = rg * 8 + 2 * q, n = bn + cp * 2 + c;
                int i0 = r * HH + n, i1 = i0 + HH;
                float za = g_z0[i0], zb = g_z0[i1];
                h0n[i0] = (1.f - za) * h0[i0] + za * sigm(va + X[i0]);
                h0n[i1] = (1.f - zb) * h0[i1] + zb * sigm(vb + X[i1]);
            }
    }
}

// x1[px] = sigm(h0[ph] @ Wfc + bfc)
__global__ __launch_bounds__(512, 1) void k_fc(int ph, int px,
    const float* __restrict__ Wfc, const float* __restrict__ bfc)
{
    const int bn = blockIdx.x * 16;
    ull acc[8];
    stage_core<16, HH, HH>(g_h0[ph], g_h0[ph], Wfc, bn, acc);
    if (threadIdx.x < 64) {
        const int u = threadIdx.x, rg = u >> 3, cp = u & 7;
        float* x1 = g_x1[px];
#pragma unroll
        for (int q = 0; q < 4; q++)
#pragma unroll
            for (int c = 0; c < 2; c++) {
                float va, vb; unpk(acc[2 * q + c], va, vb);
                int r = rg * 8 + 2 * q, n = bn + cp * 2 + c;
                x1[r * HH + n]       = sigm(va + bfc[n]);
                x1[(r + 1) * HH + n] = sigm(vb + bfc[n]);
            }
    }
}

// r1 & z1 over [x1[p] | h1], K=2048, gates folded into N=2048. Writes rh1 / z1.
__global__ __launch_bounds__(512, 1) void k_g1(int p,
    const float* __restrict__ Wr1, const float* __restrict__ Wz1,
    const float* __restrict__ br1, const float* __restrict__ bz1)
{
    const int g = blockIdx.x * 32;
    const int gate = g >> 10, bn = g & (HH - 1);
    const float* W = gate ? Wz1 : Wr1;
    ull acc[8];
    stage_core<32, 2 * HH, HH>(g_x1[p], g_h1, W, bn, acc);
    if (threadIdx.x < 128) {
        const int u = threadIdx.x, rg = u >> 4, cp = u & 15;
        const float* bias = gate ? bz1 : br1;
#pragma unroll
        for (int q = 0; q < 4; q++)
#pragma unroll
            for (int c = 0; c < 2; c++) {
                float va, vb; unpk(acc[2 * q + c], va, vb);
                int r = rg * 8 + 2 * q, n = bn + cp * 2 + c;
                int i0 = r * HH + n, i1 = i0 + HH;
                float s0 = sigm(va + bias[n]);
                float s1 = sigm(vb + bias[n]);
                if (gate == 0) { g_rh1[i0] = s0 * g_h1[i0]; g_rh1[i1] = s1 * g_h1[i1]; }
                else           { g_z1[i0] = s0;             g_z1[i1] = s1; }
            }
    }
}

// hh1 over [x1[p] | rh1]; h1 = (1-z1)h1 + z1*hh1; store H1all[ts]
__global__ __launch_bounds__(512, 1) void k_c1(int p, int ts,
    const float* __restrict__ Wh1, const float* __restrict__ bh1)
{
    const int bn = blockIdx.x * 16;
    ull acc[8];
    stage_core<16, 2 * HH, HH>(g_x1[p], g_rh1, Wh1, bn, acc);
    if (threadIdx.x < 64) {
        const int u = threadIdx.x, rg = u >> 3, cp = u & 7;
#pragma unroll
        for (int q = 0; q < 4; q++)
#pragma unroll
            for (int c = 0; c < 2; c++) {
                float va, vb; unpk(acc[2 * q + c], va, vb);
                int r = rg * 8 + 2 * q, n = bn + cp * 2 + c;
#pragma unroll
                for (int s = 0; s < 2; s++) {
                    int idx = (r + s) * HH + n;
                    float hv = (s == 0) ? va : vb;
                    float hh = sigm(hv + bh1[n]);
                    float h1 = g_h1[idx], z = g_z1[idx];
                    float hn = (1.f - z) * h1 + z * hh;
                    g_h1[idx] = hn;
                    g_H1all[(size_t)ts * BH + idx] = hn;
                }
            }
    }
}

// h_final = [h0, h1]  (SS even -> final h0 parity 0)
__global__ void k_hfinal(float* __restrict__ out) {
    int i = blockIdx.x * blockDim.x + threadIdx.x;
    if (i < BH) {
        out[i]      = g_h0[0][i];
        out[BH + i] = g_h1[i];
    }
}

extern "C" void kernel_launch(void* const* d_in, const int* in_sizes, int n_in,
                              void* d_out, int out_size)
{
    const int*   ids    = (const int*)d_in[0];
    const float* h_init = (const float*)d_in[1];
    const float* emb    = (const float*)d_in[2];
    const float* Wr0 = (const float*)d_in[3],  *Wz0 = (const float*)d_in[4],  *Wh0 = (const float*)d_in[5];
    const float* br0 = (const float*)d_in[6],  *bz0 = (const float*)d_in[7],  *bh0 = (const float*)d_in[8];
    const float* Wr1 = (const float*)d_in[9],  *Wz1 = (const float*)d_in[10], *Wh1 = (const float*)d_in[11];
    const float* br1 = (const float*)d_in[12], *bz1 = (const float*)d_in[13], *bh1 = (const float*)d_in[14];
    const float* Wfc = (const float*)d_in[15], *bfc = (const float*)d_in[16];
    const float* Wout = (const float*)d_in[17], *bout = (const float*)d_in[18];
    float* out = (float*)d_out;

    // one-time host objects (created on the first, non-captured, correctness call)
    static bool s_init = false;
    static cudaStream_t sB, sC;
    static cudaEvent_t evStart, evC0, evFcP[2], evC1P[2], evB, evC;
    if (!s_init) {
        cudaStreamCreateWithFlags(&sB, cudaStreamNonBlocking);
        cudaStreamCreateWithFlags(&sC, cudaStreamNonBlocking);
        cudaEventCreateWithFlags(&evStart,  cudaEventDisableTiming);
        cudaEventCreateWithFlags(&evC0,     cudaEventDisableTiming);
        cudaEventCreateWithFlags(&evFcP[0], cudaEventDisableTiming);
        cudaEventCreateWithFlags(&evFcP[1], cudaEventDisableTiming);
        cudaEventCreateWithFlags(&evC1P[0], cudaEventDisableTiming);
        cudaEventCreateWithFlags(&evC1P[1], cudaEventDisableTiming);
        cudaEventCreateWithFlags(&evB,      cudaEventDisableTiming);
        cudaEventCreateWithFlags(&evC,      cudaEventDisableTiming);
        s_init = true;
    }

    cudaFuncSetAttribute(k_g0, cudaFuncAttributeMaxDynamicSharedMemorySize, SM32);
    cudaFuncSetAttribute(k_g1, cudaFuncAttributeMaxDynamicSharedMemorySize, SM32);
    cudaFuncSetAttribute(k_c0, cudaFuncAttributeMaxDynamicSharedMemorySize, SM16);
    cudaFuncSetAttribute(k_fc, cudaFuncAttributeMaxDynamicSharedMemorySize, SM16);
    cudaFuncSetAttribute(k_c1, cudaFuncAttributeMaxDynamicSharedMemorySize, SM16);

    k_init<<<(BH + 255) / 256, 256>>>(h_init);
    k_embed<<<dim3(HH / 64, (SS * BB) / 64, 3), 256>>>(ids, emb, Wr0, Wz0, Wh0, br0, bz0, bh0);

    // fork sB / sC off the main (legacy) stream
    cudaEventRecord(evStart, 0);
    cudaStreamWaitEvent(sB, evStart, 0);
    cudaStreamWaitEvent(sC, evStart, 0);
    // pre-record parity handles so the first waits are valid in capture
    cudaEventRecord(evFcP[0], sB); cudaEventRecord(evFcP[1], sB);
    cudaEventRecord(evC1P[0], sC); cudaEventRecord(evC1P[1], sC);

    for (int t = 0; t < SS; ++t) {
        const int p = t & 1;
        // ---- layer-0 chain on the main stream ----
        if (t >= 2) cudaStreamWaitEvent(0, evFcP[p], 0);   // WAR: c0(t) overwrites h0 read by fc(t-2)
        k_g0<<<64, 512, SM32, 0>>>(p, t, Wr0, Wz0);
        k_c0<<<64, 512, SM16, 0>>>(p, t, Wh0);
        cudaEventRecord(evC0, 0);
        // ---- fc on stream B ----
        cudaStreamWaitEvent(sB, evC0, 0);
        if (t >= 2) cudaStreamWaitEvent(sB, evC1P[p], 0);  // WAR: fc(t) overwrites x1 read by g1/c1(t-2)
        k_fc<<<64, 512, SM16, sB>>>(p ^ 1, p, Wfc, bfc);
        cudaEventRecord(evFcP[p], sB);
        // ---- layer-1 chain on stream C ----
        cudaStreamWaitEvent(sC, evFcP[p], 0);
        k_g1<<<64, 512, SM32, sC>>>(p, Wr1, Wz1, br1, bz1);
        k_c1<<<64, 512, SM16, sC>>>(p, t, Wh1, bh1);
        cudaEventRecord(evC1P[p], sC);
    }

    // join
    cudaEventRecord(evB, sB);
    cudaEventRecord(evC, sC);
    cudaStreamWaitEvent(0, evB, 0);
    cudaStreamWaitEvent(0, evC, 0);

    k_out<<<dim3((VV + 63) / 64, (SS * BB) / 64), 256>>>(Wout, bout, out);
    k_hfinal<<<(BH + 255) / 256, 256>>>(out + (size_t)SS * BB * VV);
}